// round 9
// baseline (speedup 1.0000x reference)
#include <cuda_runtime.h>
#include <cstdint>

// GNN critic encoder, fully fused: one CTA per batch row.
// R7 = R6 + build fix: warp-private cp.async double-buffered weight staging
// (zero GEMM CTA-barriers), f32x2 packed FMA, register-side weight dup,
// warp-per-head mapping.

#define HSTRIDE 1032   // h2 per-head stride (words); 1032 % 32 == 8
#define XTS 36         // xt per-feature stride (words); %4==0 (16B align)

typedef unsigned long long ull;

__device__ __forceinline__ ull fma2(ull a, ull b, ull c) {
    ull d;
    asm("fma.rn.f32x2 %0, %1, %2, %3;" : "=l"(d) : "l"(a), "l"(b), "l"(c));
    return d;
}
__device__ __forceinline__ ull pack2(float lo, float hi) {
    ull r;
    asm("mov.b64 %0, {%1, %2};" : "=l"(r) : "f"(lo), "f"(hi));
    return r;
}
__device__ __forceinline__ void unpack2(ull v, float& lo, float& hi) {
    asm("mov.b64 {%0, %1}, %2;" : "=f"(lo), "=f"(hi) : "l"(v));
}
__device__ __forceinline__ ull dup2(float v) { return pack2(v, v); }

__device__ __forceinline__ float elu1(float v) { return v > 0.f ? v : expm1f(v); }

__device__ __forceinline__ unsigned int smem_u32(const void* p) {
    return (unsigned int)__cvta_generic_to_shared(p);
}

// Token embedding -> xt (feature-major). Cols per thread: lane, lane+32, lane+64, lane+96.
template<int D>
__device__ __forceinline__ void embed_tokens(const float* __restrict__ obs_tok,
                                             const float* __restrict__ W,
                                             const float* __restrict__ bias,
                                             float* __restrict__ xt,
                                             int t0, int lane)
{
    float bb[4];
#pragma unroll
    for (int c = 0; c < 4; c++) bb[c] = __ldg(&bias[lane + 32 * c]);
    float acc[8][4];
#pragma unroll
    for (int r = 0; r < 8; r++)
#pragma unroll
        for (int c = 0; c < 4; c++) acc[r][c] = bb[c];
#pragma unroll 4
    for (int d = 0; d < D; d++) {
        float wv[4];
#pragma unroll
        for (int c = 0; c < 4; c++) wv[c] = __ldg(&W[d * 128 + lane + 32 * c]);
#pragma unroll
        for (int r = 0; r < 8; r++) {
            float xv = obs_tok[r * D + d];
#pragma unroll
            for (int c = 0; c < 4; c++) acc[r][c] += xv * wv[c];
        }
    }
#pragma unroll
    for (int r = 0; r < 8; r++)
#pragma unroll
        for (int c = 0; c < 4; c++)
            xt[(lane + 32 * c) * XTS + (t0 + r)] = acc[r][c];
}

__global__ __launch_bounds__(128, 4)
void gnn_critic_kernel(const float* __restrict__ gobs,
                       const float* __restrict__ Wv, const float* __restrict__ bv,
                       const float* __restrict__ Wp, const float* __restrict__ bp,
                       const float* __restrict__ w0g, const float* __restrict__ as0,
                       const float* __restrict__ ad0,
                       const float* __restrict__ w1g, const float* __restrict__ as1,
                       const float* __restrict__ ad1,
                       float* __restrict__ out)
{
    __shared__ float xt[128 * XTS];                   // activations, feature-major [f][token]
    __shared__ float h2[4 * HSTRIDE];                 // h = x@w, head-strided [head][tok*32+d]
    __shared__ __align__(16) float wbuf[4][2][512];   // per-warp 2-stage ring: 16 k x 32 cols
    __shared__ float as_sh[128];                      // [head*32 + token]
    __shared__ float ad_sh[128];
    __shared__ float alive[32];
    __shared__ float inv_cnt_sh;

    float* obs = &wbuf[0][0][0];                      // 1056 floats <= 4096; dead before staging

    const int tid  = threadIdx.x;
    const int lane = tid & 31;
    const int warp = tid >> 5;                        // == head
    const int b    = blockIdx.x;

    // ---- load obs row ----
    const float* rowp = gobs + (long)b * 1056;
    for (int i = tid; i < 1056; i += 128) obs[i] = __ldg(&rowp[i]);
    __syncthreads();

    // ---- alive mask + all-dead fix + pool count ----
    if (warp == 0) {
        float v = (obs[1024 + lane] >= 0.5f) ? 1.0f : 0.0f;
        float s = v;
#pragma unroll
        for (int o = 16; o; o >>= 1) s += __shfl_xor_sync(0xffffffffu, s, o);
        float vv = (s < 0.5f) ? 1.0f : v;
        alive[lane] = vv;
        if (lane == 0) {
            float cnt = (s < 0.5f) ? 32.0f : s;
            inv_cnt_sh = 1.0f / fmaxf(cnt, 1.0f);
        }
    }
    __syncthreads();

    // ---- token embedding: warps 0-1 vehicles (D=40), warps 2-3 peds (D=24) ----
    if (warp < 2)
        embed_tokens<40>(obs + warp * 8 * 40, Wv, bv, xt, warp * 8, lane);
    else
        embed_tokens<24>(obs + 640 + (warp - 2) * 8 * 24, Wp, bp, xt, warp * 8, lane);
    __syncthreads();          // xt + alive ready; obs dead -> staging may begin

    const int lq = lane & 7;                 // col quad within head: local cols lq*4..lq*4+3
    const int t0 = (lane >> 3) * 8;          // token base: 8 tokens per lane
    const unsigned int wb_base = smem_u32(&wbuf[warp][0][0]);

    // per-warp async prefetch of 16x32 weight slice (head cols) into stage s
    auto prefetch = [&](const float* __restrict__ w, int kb, int s) {
        const int c = lane;                  // 4 rounds x 32 lanes x 16B = 2KB
#pragma unroll
        for (int r2 = 0; r2 < 4; r2++) {
            const int ch = r2 * 32 + c;      // 16B chunk index: row = ch/8, sub = ch%8
            const float* g = w + kb * 2048 + (ch >> 3) * 128 + warp * 32 + (ch & 7) * 4;
            unsigned int sp = wb_base + (unsigned int)(s * 2048 + ch * 16);
            asm volatile("cp.async.cg.shared.global [%0], [%1], 16;\n" :: "r"(sp), "l"(g));
        }
        asm volatile("cp.async.commit_group;\n");
    };

    prefetch(w0g, 0, 0);
    prefetch(w0g, 1, 1);

    for (int L = 0; L < 2; L++) {
        const float* w    = L ? w1g : w0g;
        const float* asrc = L ? as1 : as0;
        const float* adst = L ? ad1 : ad0;

        // ---- GEMM: h = x @ w. warp = head (32 cols). No CTA barriers. ----
        ull acc[4][4];
#pragma unroll
        for (int rp = 0; rp < 4; rp++)
#pragma unroll
            for (int c = 0; c < 4; c++) acc[rp][c] = 0ull;

#pragma unroll 1
        for (int kb = 0; kb < 8; kb++) {
            if (kb == 7) asm volatile("cp.async.wait_group 0;\n" ::: "memory");
            else         asm volatile("cp.async.wait_group 1;\n" ::: "memory");
            __syncwarp();
            const float* ws = &wbuf[warp][kb & 1][0];
#pragma unroll 4
            for (int kk = 0; kk < 16; kk++) {
                const int k = kb * 16 + kk;
                const ulonglong2* xp = (const ulonglong2*)&xt[k * XTS + t0];
                ulonglong2 xa = xp[0];                       // tokens (t0..t0+3)
                ulonglong2 xb = xp[1];                       // tokens (t0+4..t0+7)
                float4 wf = *(const float4*)&ws[kk * 32 + lq * 4];
                ull w0d = dup2(wf.x), w1d = dup2(wf.y);
                ull w2d = dup2(wf.z), w3d = dup2(wf.w);
                acc[0][0] = fma2(w0d, xa.x, acc[0][0]);
                acc[0][1] = fma2(w1d, xa.x, acc[0][1]);
                acc[0][2] = fma2(w2d, xa.x, acc[0][2]);
                acc[0][3] = fma2(w3d, xa.x, acc[0][3]);
                acc[1][0] = fma2(w0d, xa.y, acc[1][0]);
                acc[1][1] = fma2(w1d, xa.y, acc[1][1]);
                acc[1][2] = fma2(w2d, xa.y, acc[1][2]);
                acc[1][3] = fma2(w3d, xa.y, acc[1][3]);
                acc[2][0] = fma2(w0d, xb.x, acc[2][0]);
                acc[2][1] = fma2(w1d, xb.x, acc[2][1]);
                acc[2][2] = fma2(w2d, xb.x, acc[2][2]);
                acc[2][3] = fma2(w3d, xb.x, acc[2][3]);
                acc[3][0] = fma2(w0d, xb.y, acc[3][0]);
                acc[3][1] = fma2(w1d, xb.y, acc[3][1]);
                acc[3][2] = fma2(w2d, xb.y, acc[3][2]);
                acc[3][3] = fma2(w3d, xb.y, acc[3][3]);
            }
            // refill this stage: kb+2 of current layer, or first blocks of next layer
            if (kb < 6)           prefetch(w,   kb + 2, kb & 1);
            else if (L == 0)      prefetch(w1g, kb - 6, kb & 1);   // kb6->w1 k0 s0, kb7->w1 k1 s1
        }
        // write h2 (head-strided, token-major rows)
#pragma unroll
        for (int rp = 0; rp < 4; rp++) {
            float lo0, hi0, lo1, hi1, lo2, hi2, lo3, hi3;
            unpack2(acc[rp][0], lo0, hi0);
            unpack2(acc[rp][1], lo1, hi1);
            unpack2(acc[rp][2], lo2, hi2);
            unpack2(acc[rp][3], lo3, hi3);
            float* base = &h2[warp * HSTRIDE + (t0 + 2 * rp) * 32 + lq * 4];
            *(float4*)base        = make_float4(lo0, lo1, lo2, lo3);
            *(float4*)(base + 32) = make_float4(hi0, hi1, hi2, hi3);
        }
        __syncwarp();      // h2 head-slice complete (warp-local)

        // ---- alpha_src / alpha_dst : warp = head, lane = token ----
        {
            const float* hrow = &h2[warp * HSTRIDE + lane * 32];
            float sa = 0.f, sd = 0.f;
#pragma unroll
            for (int q = 0; q < 8; q++) {
                const int d4 = (q + lane) & 7;       // rotate: spread banks
                float4 hv = *(const float4*)&hrow[d4 * 4];
                float4 a1 = __ldg((const float4*)&asrc[warp * 32 + d4 * 4]);
                float4 a2 = __ldg((const float4*)&adst[warp * 32 + d4 * 4]);
                sa += hv.x * a1.x + hv.y * a1.y + hv.z * a1.z + hv.w * a1.w;
                sd += hv.x * a2.x + hv.y * a2.y + hv.z * a2.z + hv.w * a2.w;
            }
            as_sh[warp * 32 + lane] = sa;
            ad_sh[warp * 32 + lane] = sd;
        }
        __syncwarp();

        // ---- attention + aggregate + ELU : warp = head, lane = query i ----
        {
            const int i = lane;
            const float a_i = as_sh[warp * 32 + i];
            float p[32];
            float m = -1e30f;
#pragma unroll
            for (int j = 0; j < 32; j++) {
                float e = a_i + ad_sh[warp * 32 + j];   // broadcast
                e = fmaxf(e, 0.2f * e);                 // leaky relu
                p[j] = (alive[j] > 0.5f) ? e : -1e30f;  // mask
                m = fmaxf(m, p[j]);
            }
            float s = 0.f;
#pragma unroll
            for (int j = 0; j < 32; j++) { p[j] = __expf(p[j] - m); s += p[j]; }
            const float inv = 1.0f / s;

            const ulonglong2* hb = (const ulonglong2*)&h2[warp * HSTRIDE];
            ull agg[16];
#pragma unroll
            for (int d = 0; d < 16; d++) agg[d] = 0ull;
#pragma unroll 2
            for (int j = 0; j < 32; j++) {
                ull pj = dup2(p[j]);
#pragma unroll
                for (int d2 = 0; d2 < 8; d2++) {
                    ulonglong2 hv = hb[j * 8 + d2];     // broadcast, 16B
                    agg[2 * d2]     = fma2(pj, hv.x, agg[2 * d2]);
                    agg[2 * d2 + 1] = fma2(pj, hv.y, agg[2 * d2 + 1]);
                }
            }
            // normalize + ELU, store feature-major for next GEMM / pool
#pragma unroll
            for (int d2 = 0; d2 < 8; d2++) {
                float v0, v1, v2, v3;
                unpack2(agg[2 * d2],     v0, v1);
                unpack2(agg[2 * d2 + 1], v2, v3);
                v0 = elu1(v0 * inv); v1 = elu1(v1 * inv);
                v2 = elu1(v2 * inv); v3 = elu1(v3 * inv);
                const int f = warp * 32 + d2 * 4;
                xt[(f + 0) * XTS + i] = v0;
                xt[(f + 1) * XTS + i] = v1;
                xt[(f + 2) * XTS + i] = v2;
                xt[(f + 3) * XTS + i] = v3;
            }
        }
        __syncthreads();   // xt fully rewritten (all heads) before next GEMM / pool
    }

    // ---- masked mean pool: thread = output feature, float4 over tokens ----
    {
        float s = 0.f;
        const float4* xf = (const float4*)&xt[tid * XTS];
        const float4* al = (const float4*)alive;
#pragma unroll
        for (int q = 0; q < 8; q++) {
            float4 x4 = xf[q];
            float4 a4 = al[q];
            s += a4.x * x4.x + a4.y * x4.y + a4.z * x4.z + a4.w * x4.w;
        }
        out[(long)b * 128 + tid] = s * inv_cnt_sh;
    }
}

extern "C" void kernel_launch(void* const* d_in, const int* in_sizes, int n_in,
                              void* d_out, int out_size)
{
    const float* gobs = (const float*)d_in[0];
    const float* Wv   = (const float*)d_in[1];
    const float* bv   = (const float*)d_in[2];
    const float* Wp   = (const float*)d_in[3];
    const float* bp   = (const float*)d_in[4];
    const float* w0   = (const float*)d_in[5];
    const float* as0  = (const float*)d_in[6];
    const float* ad0  = (const float*)d_in[7];
    const float* w1   = (const float*)d_in[8];
    const float* as1  = (const float*)d_in[9];
    const float* ad1  = (const float*)d_in[10];

    const int B = in_sizes[0] / 1056;

    gnn_critic_kernel<<<B, 128>>>(gobs, Wv, bv, Wp, bp,
                                  w0, as0, ad0, w1, as1, ad1,
                                  (float*)d_out);
}

// round 11
// speedup vs baseline: 2.1317x; 2.1317x over previous
#include <cuda_runtime.h>
#include <cstdint>

// GNN critic encoder, fully fused: one CTA per batch row.
// R9: tf32 mma.sync tensor-core GEMMs with hi/lo error compensation (3-term),
//     per-warp cp.async weight ring, alpha from MMA fragments, scalar attention.

#define XSROW 132      // xs token-row stride (words): 132 % 32 == 4 -> A-frag reads conflict-free
#define HSTRIDE 1032   // h2 per-head stride (words), row stride 32

__device__ __forceinline__ float elu1(float v) { return v > 0.f ? v : expm1f(v); }

__device__ __forceinline__ unsigned int smem_u32(const void* p) {
    return (unsigned int)__cvta_generic_to_shared(p);
}

// tf32 split: hi = top 10 mantissa bits (valid tf32), lo = exact residual
__device__ __forceinline__ void split_tf32(float v, unsigned& hi, unsigned& lo) {
    unsigned u = __float_as_uint(v) & 0xFFFFE000u;
    hi = u;
    lo = __float_as_uint(v - __uint_as_float(u));
}

__device__ __forceinline__ void mma_tf32(float c[4],
                                         unsigned a0, unsigned a1, unsigned a2, unsigned a3,
                                         unsigned b0, unsigned b1) {
    asm volatile(
        "mma.sync.aligned.m16n8k8.row.col.f32.tf32.tf32.f32 "
        "{%0,%1,%2,%3}, {%4,%5,%6,%7}, {%8,%9}, {%0,%1,%2,%3};"
        : "+f"(c[0]), "+f"(c[1]), "+f"(c[2]), "+f"(c[3])
        : "r"(a0), "r"(a1), "r"(a2), "r"(a3), "r"(b0), "r"(b1));
}

// Token embedding -> xs (token-major [32][XSROW]). Cols: lane, lane+32, lane+64, lane+96.
template<int D>
__device__ __forceinline__ void embed_tokens(const float* __restrict__ obs_tok,
                                             const float* __restrict__ W,
                                             const float* __restrict__ bias,
                                             float* __restrict__ xs,
                                             int t0, int lane)
{
    float bb[4];
#pragma unroll
    for (int c = 0; c < 4; c++) bb[c] = __ldg(&bias[lane + 32 * c]);
    float acc[8][4];
#pragma unroll
    for (int r = 0; r < 8; r++)
#pragma unroll
        for (int c = 0; c < 4; c++) acc[r][c] = bb[c];
#pragma unroll 4
    for (int d = 0; d < D; d++) {
        float wv[4];
#pragma unroll
        for (int c = 0; c < 4; c++) wv[c] = __ldg(&W[d * 128 + lane + 32 * c]);
#pragma unroll
        for (int r = 0; r < 8; r++) {
            float xv = obs_tok[r * D + d];
#pragma unroll
            for (int c = 0; c < 4; c++) acc[r][c] += xv * wv[c];
        }
    }
#pragma unroll
    for (int r = 0; r < 8; r++)
#pragma unroll
        for (int c = 0; c < 4; c++)
            xs[(t0 + r) * XSROW + lane + 32 * c] = acc[r][c];
}

__global__ __launch_bounds__(128, 4)
void gnn_critic_kernel(const float* __restrict__ gobs,
                       const float* __restrict__ Wv, const float* __restrict__ bv,
                       const float* __restrict__ Wp, const float* __restrict__ bp,
                       const float* __restrict__ w0g, const float* __restrict__ as0,
                       const float* __restrict__ ad0,
                       const float* __restrict__ w1g, const float* __restrict__ as1,
                       const float* __restrict__ ad1,
                       float* __restrict__ out)
{
    __shared__ float xs[32 * XSROW];                  // activations, token-major
    __shared__ float h2[4 * HSTRIDE];                 // h = x@w, [head][token*32+d]
    __shared__ __align__(16) float wbuf[4 * 2 * 320]; // per-warp 2-stage ring: 8k x 40(pad) words
    __shared__ float as_sh[128];                      // [head*32 + token]
    __shared__ float ad_sh[128];
    __shared__ float alive[32];
    __shared__ float inv_cnt_sh;

    float* obs = wbuf;                                // 1056 floats <= 2560; dead before staging

    const int tid  = threadIdx.x;
    const int lane = tid & 31;
    const int warp = tid >> 5;                        // == head
    const int b    = blockIdx.x;
    const int g    = lane >> 2;                       // mma group (row within tile)
    const int tig  = lane & 3;                        // thread-in-group (k / col pair)

    // ---- load obs row ----
    const float* rowp = gobs + (long)b * 1056;
    for (int i = tid; i < 1056; i += 128) obs[i] = __ldg(&rowp[i]);
    __syncthreads();

    // ---- alive mask + all-dead fix + pool count ----
    if (warp == 0) {
        float v = (obs[1024 + lane] >= 0.5f) ? 1.0f : 0.0f;
        float s = v;
#pragma unroll
        for (int o = 16; o; o >>= 1) s += __shfl_xor_sync(0xffffffffu, s, o);
        float vv = (s < 0.5f) ? 1.0f : v;
        alive[lane] = vv;
        if (lane == 0) {
            float cnt = (s < 0.5f) ? 32.0f : s;
            inv_cnt_sh = 1.0f / fmaxf(cnt, 1.0f);
        }
    }
    __syncthreads();

    // ---- token embedding ----
    if (warp < 2)
        embed_tokens<40>(obs + warp * 8 * 40, Wv, bv, xs, warp * 8, lane);
    else
        embed_tokens<24>(obs + 640 + (warp - 2) * 8 * 24, Wp, bp, xs, warp * 8, lane);
    __syncthreads();          // xs ready; obs dead -> weight staging may begin

    const unsigned wb_base = smem_u32(wbuf + warp * 640);

    // per-warp async prefetch of an 8x32 weight slice (head cols) into stage s, [8][40] layout
    auto prefetch = [&](const float* __restrict__ w, int kb, int s) {
#pragma unroll
        for (int it = 0; it < 2; it++) {
            const int ch  = it * 32 + lane;          // 64 chunks of 16B
            const int row = ch >> 3, sub = ch & 7;
            const float* gp = w + (kb * 8 + row) * 128 + warp * 32 + sub * 4;
            unsigned sp = wb_base + (unsigned)(s * 1280 + row * 160 + sub * 16);
            asm volatile("cp.async.cg.shared.global [%0], [%1], 16;\n" :: "r"(sp), "l"(gp));
        }
        asm volatile("cp.async.commit_group;\n");
    };

    prefetch(w0g, 0, 0);
    prefetch(w0g, 1, 1);

    for (int L = 0; L < 2; L++) {
        const float* w    = L ? w1g : w0g;
        const float* asrc = L ? as1 : as0;
        const float* adst = L ? ad1 : ad0;

        // ---- GEMM: h = x @ w via tf32 mma, 3-term compensated. warp = head. ----
        float C[2][4][4];                    // [mtile][ntile][frag]
#pragma unroll
        for (int mt = 0; mt < 2; mt++)
#pragma unroll
            for (int nt = 0; nt < 4; nt++)
#pragma unroll
                for (int r = 0; r < 4; r++) C[mt][nt][r] = 0.f;

#pragma unroll 1
        for (int kb = 0; kb < 16; kb++) {    // one k8 step per kb
            if (L == 1 && kb == 15) asm volatile("cp.async.wait_group 0;\n" ::: "memory");
            else                    asm volatile("cp.async.wait_group 1;\n" ::: "memory");
            __syncwarp();

            // A fragments (both m-tiles), split hi/lo
            unsigned ah[2][4], al[2][4];
#pragma unroll
            for (int mt = 0; mt < 2; mt++) {
                const int r0 = (mt * 16 + g) * XSROW + kb * 8 + tig;
                split_tf32(xs[r0],                ah[mt][0], al[mt][0]);
                split_tf32(xs[r0 + 8 * XSROW],    ah[mt][1], al[mt][1]);
                split_tf32(xs[r0 + 4],            ah[mt][2], al[mt][2]);
                split_tf32(xs[r0 + 8 * XSROW + 4],ah[mt][3], al[mt][3]);
            }
            const float* ws = wbuf + warp * 640 + (kb & 1) * 320;
#pragma unroll
            for (int nt = 0; nt < 4; nt++) {
                unsigned bh0, bl0, bh1, bl1;
                split_tf32(ws[tig * 40 + nt * 8 + g],       bh0, bl0);
                split_tf32(ws[(tig + 4) * 40 + nt * 8 + g], bh1, bl1);
#pragma unroll
                for (int mt = 0; mt < 2; mt++) {
                    mma_tf32(C[mt][nt], ah[mt][0], ah[mt][1], ah[mt][2], ah[mt][3], bh0, bh1);
                    mma_tf32(C[mt][nt], ah[mt][0], ah[mt][1], ah[mt][2], ah[mt][3], bl0, bl1);
                    mma_tf32(C[mt][nt], al[mt][0], al[mt][1], al[mt][2], al[mt][3], bh0, bh1);
                }
            }
            // refill this stage
            if (kb < 14)      prefetch(w,   kb + 2,  kb & 1);
            else if (L == 0)  prefetch(w1g, kb - 14, kb & 1);   // cross into layer-1 weights
        }

        // ---- alpha from fragments: quad-reduce over tig ----
        {
            float sa[4] = {0.f, 0.f, 0.f, 0.f};
            float sd[4] = {0.f, 0.f, 0.f, 0.f};
#pragma unroll
            for (int nt = 0; nt < 4; nt++) {
                float2 av = __ldg((const float2*)&asrc[warp * 32 + nt * 8 + 2 * tig]);
                float2 dv = __ldg((const float2*)&adst[warp * 32 + nt * 8 + 2 * tig]);
#pragma unroll
                for (int mt = 0; mt < 2; mt++) {
                    sa[mt*2+0] += C[mt][nt][0] * av.x + C[mt][nt][1] * av.y;
                    sa[mt*2+1] += C[mt][nt][2] * av.x + C[mt][nt][3] * av.y;
                    sd[mt*2+0] += C[mt][nt][0] * dv.x + C[mt][nt][1] * dv.y;
                    sd[mt*2+1] += C[mt][nt][2] * dv.x + C[mt][nt][3] * dv.y;
                }
            }
#pragma unroll
            for (int tm = 0; tm < 4; tm++) {
                sa[tm] += __shfl_xor_sync(0xffffffffu, sa[tm], 1);
                sa[tm] += __shfl_xor_sync(0xffffffffu, sa[tm], 2);
                sd[tm] += __shfl_xor_sync(0xffffffffu, sd[tm], 1);
                sd[tm] += __shfl_xor_sync(0xffffffffu, sd[tm], 2);
                const int token = (tm >> 1) * 16 + (tm & 1) * 8 + g;
                as_sh[warp * 32 + token] = sa[tm];   // 4 lanes write same value: benign
                ad_sh[warp * 32 + token] = sd[tm];
            }
        }

        // ---- store h2 from fragments ----
#pragma unroll
        for (int mt = 0; mt < 2; mt++)
#pragma unroll
            for (int nt = 0; nt < 4; nt++) {
                float* hp = &h2[warp * HSTRIDE + (mt * 16 + g) * 32 + nt * 8 + 2 * tig];
                *(float2*)hp            = make_float2(C[mt][nt][0], C[mt][nt][1]);
                *(float2*)(hp + 8 * 32) = make_float2(C[mt][nt][2], C[mt][nt][3]);
            }
        __syncthreads();   // all warps done reading xs (GEMM) before attention rewrites it

        // ---- attention + aggregate + ELU : warp = head, lane = query i ----
        {
            const int i = lane;
            const float a_i = as_sh[warp * 32 + i];
            float p[32];
            float m = -1e30f;
#pragma unroll
            for (int j = 0; j < 32; j++) {
                float e = a_i + ad_sh[warp * 32 + j];
                e = fmaxf(e, 0.2f * e);                 // leaky relu
                p[j] = (alive[j] > 0.5f) ? e : -1e30f;  // mask
                m = fmaxf(m, p[j]);
            }
            float s = 0.f;
#pragma unroll
            for (int j = 0; j < 32; j++) { p[j] = __expf(p[j] - m); s += p[j]; }
            const float inv = 1.0f / s;

            const float4* hb = (const float4*)&h2[warp * HSTRIDE];
            float4 acc4[8];
#pragma unroll
            for (int d2 = 0; d2 < 8; d2++) acc4[d2] = make_float4(0.f, 0.f, 0.f, 0.f);
#pragma unroll 2
            for (int j = 0; j < 32; j++) {
                const float pj = p[j];
#pragma unroll
                for (int d2 = 0; d2 < 8; d2++) {
                    float4 hv = hb[j * 8 + d2];         // broadcast 16B
                    acc4[d2].x += pj * hv.x; acc4[d2].y += pj * hv.y;
                    acc4[d2].z += pj * hv.z; acc4[d2].w += pj * hv.w;
                }
            }
#pragma unroll
            for (int q = 0; q < 8; q++) {
                float4 o;
                o.x = elu1(acc4[q].x * inv); o.y = elu1(acc4[q].y * inv);
                o.z = elu1(acc4[q].z * inv); o.w = elu1(acc4[q].w * inv);
                *(float4*)&xs[i * XSROW + warp * 32 + q * 4] = o;
            }
        }
        __syncthreads();   // xs fully rewritten before next GEMM / pool
    }

    // ---- masked mean pool: thread = output feature ----
    {
        float s = 0.f;
#pragma unroll
        for (int i = 0; i < 32; i++)
            s += alive[i] * xs[i * XSROW + tid];
        out[(long)b * 128 + tid] = s * inv_cnt_sh;
    }
}

extern "C" void kernel_launch(void* const* d_in, const int* in_sizes, int n_in,
                              void* d_out, int out_size)
{
    const float* gobs = (const float*)d_in[0];
    const float* Wv   = (const float*)d_in[1];
    const float* bv   = (const float*)d_in[2];
    const float* Wp   = (const float*)d_in[3];
    const float* bp   = (const float*)d_in[4];
    const float* w0   = (const float*)d_in[5];
    const float* as0  = (const float*)d_in[6];
    const float* ad0  = (const float*)d_in[7];
    const float* w1   = (const float*)d_in[8];
    const float* as1  = (const float*)d_in[9];
    const float* ad1  = (const float*)d_in[10];

    const int B = in_sizes[0] / 1056;

    gnn_critic_kernel<<<B, 128>>>(gobs, Wv, bv, Wp, bp,
                                  w0, as0, ad0, w1, as1, ad1,
                                  (float*)d_out);
}

// round 14
// speedup vs baseline: 2.4023x; 1.1269x over previous
#include <cuda_runtime.h>
#include <cstdint>

// GNN critic encoder, fully fused: one CTA per batch row.
// R11: tf32 mma for BOTH the layer GEMM (3-term compensated) and the attention
//      aggregation (2-term: p*h_hi + p*h_lo). h lives aliased in xs's head band.
//      Per-warp cp.async weight ring, alpha from GEMM fragments.

#define XSROW 132      // xs token-row stride (words): bank = 4*tok + col -> frag reads clean
#define PST   36       // pbuf row stride: bank = 4*i + j -> A-frag reads conflict-free

__device__ __forceinline__ float elu1(float v) { return v > 0.f ? v : expm1f(v); }

__device__ __forceinline__ unsigned int smem_u32(const void* p) {
    return (unsigned int)__cvta_generic_to_shared(p);
}

// tf32 split: hi = top 10 mantissa bits (valid tf32), lo = exact residual
__device__ __forceinline__ void split_tf32(float v, unsigned& hi, unsigned& lo) {
    unsigned u = __float_as_uint(v) & 0xFFFFE000u;
    hi = u;
    lo = __float_as_uint(v - __uint_as_float(u));
}
__device__ __forceinline__ unsigned hi_tf32(float v) {
    return __float_as_uint(v) & 0xFFFFE000u;
}

__device__ __forceinline__ void mma_tf32(float c[4],
                                         unsigned a0, unsigned a1, unsigned a2, unsigned a3,
                                         unsigned b0, unsigned b1) {
    asm volatile(
        "mma.sync.aligned.m16n8k8.row.col.f32.tf32.tf32.f32 "
        "{%0,%1,%2,%3}, {%4,%5,%6,%7}, {%8,%9}, {%0,%1,%2,%3};"
        : "+f"(c[0]), "+f"(c[1]), "+f"(c[2]), "+f"(c[3])
        : "r"(a0), "r"(a1), "r"(a2), "r"(a3), "r"(b0), "r"(b1));
}

// Token embedding -> xs (token-major [32][XSROW]). Cols: lane, lane+32, lane+64, lane+96.
template<int D>
__device__ __forceinline__ void embed_tokens(const float* __restrict__ obs_tok,
                                             const float* __restrict__ W,
                                             const float* __restrict__ bias,
                                             float* __restrict__ xs,
                                             int t0, int lane)
{
    float bb[4];
#pragma unroll
    for (int c = 0; c < 4; c++) bb[c] = __ldg(&bias[lane + 32 * c]);
    float acc[8][4];
#pragma unroll
    for (int r = 0; r < 8; r++)
#pragma unroll
        for (int c = 0; c < 4; c++) acc[r][c] = bb[c];
#pragma unroll 4
    for (int d = 0; d < D; d++) {
        float wv[4];
#pragma unroll
        for (int c = 0; c < 4; c++) wv[c] = __ldg(&W[d * 128 + lane + 32 * c]);
#pragma unroll
        for (int r = 0; r < 8; r++) {
            float xv = obs_tok[r * D + d];
#pragma unroll
            for (int c = 0; c < 4; c++) acc[r][c] += xv * wv[c];
        }
    }
#pragma unroll
    for (int r = 0; r < 8; r++)
#pragma unroll
        for (int c = 0; c < 4; c++)
            xs[(t0 + r) * XSROW + lane + 32 * c] = acc[r][c];
}

__global__ __launch_bounds__(128, 4)
void gnn_critic_kernel(const float* __restrict__ gobs,
                       const float* __restrict__ Wv, const float* __restrict__ bv,
                       const float* __restrict__ Wp, const float* __restrict__ bp,
                       const float* __restrict__ w0g, const float* __restrict__ as0,
                       const float* __restrict__ ad0,
                       const float* __restrict__ w1g, const float* __restrict__ as1,
                       const float* __restrict__ ad1,
                       float* __restrict__ out)
{
    __shared__ float xs[32 * XSROW];                  // activations / h (head bands alias)
    __shared__ __align__(16) float wbuf[4 * 2 * 320]; // per-warp 2-stage ring: 8k x 40(pad)
    __shared__ __align__(16) float pbuf[4][32][PST];  // per-head unnormalized attn p
    __shared__ float as_sh[128];                      // [head*32 + token]
    __shared__ float ad_sh[128];
    __shared__ float inv_sh[128];                     // per (head, query) 1/sum
    __shared__ float alive[32];
    __shared__ float inv_cnt_sh;

    float* obs = wbuf;                                // 1056 floats <= 2560; dead before staging

    const int tid  = threadIdx.x;
    const int lane = tid & 31;
    const int warp = tid >> 5;                        // == head
    const int b    = blockIdx.x;
    const int g    = lane >> 2;                       // mma group (row in tile)
    const int tig  = lane & 3;                        // thread-in-group

    // ---- load obs row ----
    const float* rowp = gobs + (long)b * 1056;
    for (int i = tid; i < 1056; i += 128) obs[i] = __ldg(&rowp[i]);
    __syncthreads();

    // ---- alive mask + all-dead fix + pool count ----
    if (warp == 0) {
        float v = (obs[1024 + lane] >= 0.5f) ? 1.0f : 0.0f;
        float s = v;
#pragma unroll
        for (int o = 16; o; o >>= 1) s += __shfl_xor_sync(0xffffffffu, s, o);
        float vv = (s < 0.5f) ? 1.0f : v;
        alive[lane] = vv;
        if (lane == 0) {
            float cnt = (s < 0.5f) ? 32.0f : s;
            inv_cnt_sh = 1.0f / fmaxf(cnt, 1.0f);
        }
    }
    __syncthreads();

    // ---- token embedding ----
    if (warp < 2)
        embed_tokens<40>(obs + warp * 8 * 40, Wv, bv, xs, warp * 8, lane);
    else
        embed_tokens<24>(obs + 640 + (warp - 2) * 8 * 24, Wp, bp, xs, warp * 8, lane);
    __syncthreads();          // xs ready; obs dead -> weight staging may begin

    const unsigned wb_base = smem_u32(wbuf + warp * 640);

    // per-warp async prefetch of an 8x32 weight slice (head cols) into stage s, [8][40]
    auto prefetch = [&](const float* __restrict__ w, int kb, int s) {
#pragma unroll
        for (int it = 0; it < 2; it++) {
            const int ch  = it * 32 + lane;          // 64 chunks of 16B
            const int row = ch >> 3, sub = ch & 7;
            const float* gp = w + (kb * 8 + row) * 128 + warp * 32 + sub * 4;
            unsigned sp = wb_base + (unsigned)(s * 1280 + row * 160 + sub * 16);
            asm volatile("cp.async.cg.shared.global [%0], [%1], 16;\n" :: "r"(sp), "l"(gp));
        }
        asm volatile("cp.async.commit_group;\n");
    };

    prefetch(w0g, 0, 0);
    prefetch(w0g, 1, 1);

    for (int L = 0; L < 2; L++) {
        const float* w    = L ? w1g : w0g;
        const float* asrc = L ? as1 : as0;
        const float* adst = L ? ad1 : ad0;

        // ---- GEMM: h = x @ w via tf32 mma, 3-term compensated. warp = head. ----
        float C[2][4][4];                    // [mtile][ntile][frag]
#pragma unroll
        for (int mt = 0; mt < 2; mt++)
#pragma unroll
            for (int nt = 0; nt < 4; nt++)
#pragma unroll
                for (int r = 0; r < 4; r++) C[mt][nt][r] = 0.f;

#pragma unroll 1
        for (int kb = 0; kb < 16; kb++) {    // one k8 step per kb
            if (L == 1 && kb == 15) asm volatile("cp.async.wait_group 0;\n" ::: "memory");
            else                    asm volatile("cp.async.wait_group 1;\n" ::: "memory");
            __syncwarp();

            unsigned ah[2][4], al[2][4];
#pragma unroll
            for (int mt = 0; mt < 2; mt++) {
                const int r0 = (mt * 16 + g) * XSROW + kb * 8 + tig;
                split_tf32(xs[r0],                 ah[mt][0], al[mt][0]);
                split_tf32(xs[r0 + 8 * XSROW],     ah[mt][1], al[mt][1]);
                split_tf32(xs[r0 + 4],             ah[mt][2], al[mt][2]);
                split_tf32(xs[r0 + 8 * XSROW + 4], ah[mt][3], al[mt][3]);
            }
            const float* ws = wbuf + warp * 640 + (kb & 1) * 320;
#pragma unroll
            for (int nt = 0; nt < 4; nt++) {
                unsigned bh0, bl0, bh1, bl1;
                split_tf32(ws[tig * 40 + nt * 8 + g],       bh0, bl0);
                split_tf32(ws[(tig + 4) * 40 + nt * 8 + g], bh1, bl1);
#pragma unroll
                for (int mt = 0; mt < 2; mt++) {
                    mma_tf32(C[mt][nt], ah[mt][0], ah[mt][1], ah[mt][2], ah[mt][3], bh0, bh1);
                    mma_tf32(C[mt][nt], ah[mt][0], ah[mt][1], ah[mt][2], ah[mt][3], bl0, bl1);
                    mma_tf32(C[mt][nt], al[mt][0], al[mt][1], al[mt][2], al[mt][3], bh0, bh1);
                }
            }
            if (kb < 14)      prefetch(w,   kb + 2,  kb & 1);
            else if (L == 0)  prefetch(w1g, kb - 14, kb & 1);
        }

        // ---- alpha from fragments: quad-reduce over tig ----
        {
            float sa[4] = {0.f, 0.f, 0.f, 0.f};
            float sd[4] = {0.f, 0.f, 0.f, 0.f};
#pragma unroll
            for (int nt = 0; nt < 4; nt++) {
                float2 av = __ldg((const float2*)&asrc[warp * 32 + nt * 8 + 2 * tig]);
                float2 dv = __ldg((const float2*)&adst[warp * 32 + nt * 8 + 2 * tig]);
#pragma unroll
                for (int mt = 0; mt < 2; mt++) {
                    sa[mt*2+0] += C[mt][nt][0] * av.x + C[mt][nt][1] * av.y;
                    sa[mt*2+1] += C[mt][nt][2] * av.x + C[mt][nt][3] * av.y;
                    sd[mt*2+0] += C[mt][nt][0] * dv.x + C[mt][nt][1] * dv.y;
                    sd[mt*2+1] += C[mt][nt][2] * dv.x + C[mt][nt][3] * dv.y;
                }
            }
#pragma unroll
            for (int tm = 0; tm < 4; tm++) {
                sa[tm] += __shfl_xor_sync(0xffffffffu, sa[tm], 1);
                sa[tm] += __shfl_xor_sync(0xffffffffu, sa[tm], 2);
                sd[tm] += __shfl_xor_sync(0xffffffffu, sd[tm], 1);
                sd[tm] += __shfl_xor_sync(0xffffffffu, sd[tm], 2);
                const int token = (tm >> 1) * 16 + (tm & 1) * 8 + g;
                as_sh[warp * 32 + token] = sa[tm];
                ad_sh[warp * 32 + token] = sd[tm];
            }
        }

        // ---- release xs (all warps finished GEMM reads), then store h into xs band ----
        __syncthreads();
#pragma unroll
        for (int mt = 0; mt < 2; mt++)
#pragma unroll
            for (int nt = 0; nt < 4; nt++) {
                float* hp = &xs[(mt * 16 + g) * XSROW + warp * 32 + nt * 8 + 2 * tig];
                *(float2*)hp              = make_float2(C[mt][nt][0], C[mt][nt][1]);
                *(float2*)(hp + 8 * XSROW) = make_float2(C[mt][nt][2], C[mt][nt][3]);
            }
        __syncwarp();

        // ---- softmax weights p (unnormalized) : lane = query i ----
        {
            const int i = lane;
            const float a_i = as_sh[warp * 32 + i];
            float p[32];
            float m = -1e30f;
#pragma unroll
            for (int j = 0; j < 32; j++) {
                float e = a_i + ad_sh[warp * 32 + j];
                e = fmaxf(e, 0.2f * e);                 // leaky relu
                p[j] = (alive[j] > 0.5f) ? e : -1e30f;  // mask
                m = fmaxf(m, p[j]);
            }
            float s = 0.f;
#pragma unroll
            for (int j = 0; j < 32; j++) { p[j] = __expf(p[j] - m); s += p[j]; }
            inv_sh[warp * 32 + i] = 1.0f / s;
            float* pr = &pbuf[warp][i][0];
#pragma unroll
            for (int q = 0; q < 8; q++)
                *(float4*)&pr[q * 4] = make_float4(p[q*4], p[q*4+1], p[q*4+2], p[q*4+3]);
        }
        __syncwarp();

        // ---- aggregation: out = (p @ h) * inv, ELU; tf32 mma 2-term ----
        {
            float Dg[2][4][4];
#pragma unroll
            for (int mt = 0; mt < 2; mt++)
#pragma unroll
                for (int nt = 0; nt < 4; nt++)
#pragma unroll
                    for (int r = 0; r < 4; r++) Dg[mt][nt][r] = 0.f;

#pragma unroll
            for (int kb = 0; kb < 4; kb++) {
                unsigned pa[2][4];
#pragma unroll
                for (int mt = 0; mt < 2; mt++) {
                    const float* pp = &pbuf[warp][mt * 16 + g][kb * 8 + tig];
                    pa[mt][0] = hi_tf32(pp[0]);
                    pa[mt][1] = hi_tf32(pp[8 * PST]);
                    pa[mt][2] = hi_tf32(pp[4]);
                    pa[mt][3] = hi_tf32(pp[8 * PST + 4]);
                }
#pragma unroll
                for (int nt = 0; nt < 4; nt++) {
                    const int col = warp * 32 + nt * 8 + g;
                    float b0f = xs[(kb * 8 + tig) * XSROW + col];
                    float b1f = xs[(kb * 8 + tig + 4) * XSROW + col];
                    unsigned bh0, bl0, bh1, bl1;
                    split_tf32(b0f, bh0, bl0);
                    split_tf32(b1f, bh1, bl1);
#pragma unroll
                    for (int mt = 0; mt < 2; mt++) {
                        mma_tf32(Dg[mt][nt], pa[mt][0], pa[mt][1], pa[mt][2], pa[mt][3], bh0, bh1);
                        mma_tf32(Dg[mt][nt], pa[mt][0], pa[mt][1], pa[mt][2], pa[mt][3], bl0, bl1);
                    }
                }
            }
            // normalize per query row, ELU, store back into the same xs band
            __syncwarp();   // all h reads done before overwriting
#pragma unroll
            for (int mt = 0; mt < 2; mt++) {
                const float inv0 = inv_sh[warp * 32 + mt * 16 + g];
                const float inv1 = inv_sh[warp * 32 + mt * 16 + g + 8];
#pragma unroll
                for (int nt = 0; nt < 4; nt++) {
                    float* op = &xs[(mt * 16 + g) * XSROW + warp * 32 + nt * 8 + 2 * tig];
                    float o0 = elu1(Dg[mt][nt][0] * inv0);
                    float o1 = elu1(Dg[mt][nt][1] * inv0);
                    float o2 = elu1(Dg[mt][nt][2] * inv1);
                    float o3 = elu1(Dg[mt][nt][3] * inv1);
                    *(float2*)op               = make_float2(o0, o1);
                    *(float2*)(op + 8 * XSROW) = make_float2(o2, o3);
                }
            }
        }
        __syncthreads();   // all head bands rewritten before next GEMM / pool
    }

    // ---- masked mean pool: thread = output feature ----
    {
        float s = 0.f;
#pragma unroll
        for (int i = 0; i < 32; i++)
            s += alive[i] * xs[i * XSROW + tid];
        out[(long)b * 128 + tid] = s * inv_cnt_sh;
    }
}

extern "C" void kernel_launch(void* const* d_in, const int* in_sizes, int n_in,
                              void* d_out, int out_size)
{
    const float* gobs = (const float*)d_in[0];
    const float* Wv   = (const float*)d_in[1];
    const float* bv   = (const float*)d_in[2];
    const float* Wp   = (const float*)d_in[3];
    const float* bp   = (const float*)d_in[4];
    const float* w0   = (const float*)d_in[5];
    const float* as0  = (const float*)d_in[6];
    const float* ad0  = (const float*)d_in[7];
    const float* w1   = (const float*)d_in[8];
    const float* as1  = (const float*)d_in[9];
    const float* ad1  = (const float*)d_in[10];

    const int B = in_sizes[0] / 1056;

    gnn_critic_kernel<<<B, 128>>>(gobs, Wv, bv, Wp, bp,
                                  w0, as0, ad0, w1, as1, ad1,
                                  (float*)d_out);
}